// round 16
// baseline (speedup 1.0000x reference)
#include <cuda_runtime.h>
#include <cuda_fp16.h>
#include <cstdint>

// MultiHeadAttention x[4,2048,1024], 16 heads, d=64, scale 1/sqrt(1024)
// fp16 mma.m16n8k16 (fp32 accum). GEMM: 512 thr, 32x32 warp tiles, 2 CTAs/SM
// (8 warps/SMSP). Attention: R13 config (128 thr, q-tile 64, register P).

#define BB 4
#define NN 2048
#define EE 1024
#define HH 16
#define DD 64
#define MM (BB*NN)      // 8192

__device__ __half g_X  [(size_t)MM*EE];     // fp16 x [M,K]
__device__ __half g_Wt [(size_t)4*EE*EE];   // fp16 W^T [N,K] x4
__device__ float  g_Bc [3*EE];              // concat bq,bk,bv (fp32)
__device__ __half g_QKV[(size_t)3*MM*EE];   // Q|K|V fp16 [b,h,n,d]
__device__ __half g_A  [(size_t)MM*EE];     // attn out fp16 [b,n,e]

// ---------------------------------------------------------------- helpers
__device__ __forceinline__ void mma16(float c[4], const uint32_t a[4], const uint32_t b[2]) {
    asm volatile("mma.sync.aligned.m16n8k16.row.col.f32.f16.f16.f32 "
                 "{%0,%1,%2,%3}, {%4,%5,%6,%7}, {%8,%9}, {%0,%1,%2,%3};\n"
                 : "+f"(c[0]), "+f"(c[1]), "+f"(c[2]), "+f"(c[3])
                 : "r"(a[0]), "r"(a[1]), "r"(a[2]), "r"(a[3]), "r"(b[0]), "r"(b[1]));
}
__device__ __forceinline__ void ldm_x4(uint32_t r[4], uint32_t addr) {
    asm volatile("ldmatrix.sync.aligned.m8n8.x4.shared.b16 {%0,%1,%2,%3}, [%4];"
                 : "=r"(r[0]), "=r"(r[1]), "=r"(r[2]), "=r"(r[3]) : "r"(addr));
}
__device__ __forceinline__ void ldm_x4t(uint32_t r[4], uint32_t addr) {
    asm volatile("ldmatrix.sync.aligned.m8n8.x4.trans.shared.b16 {%0,%1,%2,%3}, [%4];"
                 : "=r"(r[0]), "=r"(r[1]), "=r"(r[2]), "=r"(r[3]) : "r"(addr));
}
__device__ __forceinline__ void cpa16(void* smem, const void* g) {
    uint32_t s = (uint32_t)__cvta_generic_to_shared(smem);
    asm volatile("cp.async.cg.shared.global [%0], [%1], 16;\n" :: "r"(s), "l"(g));
}
#define CP_COMMIT() asm volatile("cp.async.commit_group;\n")
#define CP_WAIT0()  asm volatile("cp.async.wait_group 0;\n")
__device__ __forceinline__ uint32_t smem_u32(const void* p) {
    return (uint32_t)__cvta_generic_to_shared(p);
}
__device__ __forceinline__ uint32_t packh2(float lo, float hi) {
    __half2 h = __floats2half2_rn(lo, hi);
    return *(uint32_t*)&h;
}

// ---------------------------------------------------------------- convs
__global__ void conv_x(const float* __restrict__ src, __half* __restrict__ dst, int n4) {
    int i = blockIdx.x * blockDim.x + threadIdx.x;
    if (i < n4) {
        float4 v = ((const float4*)src)[i];
        ((__half2*)dst)[2*i]     = __floats2half2_rn(v.x, v.y);
        ((__half2*)dst)[2*i + 1] = __floats2half2_rn(v.z, v.w);
    }
}
__global__ void conv_wt(const float* W0, const float* W1, const float* W2,
                        const float* W3, __half* __restrict__ Wt) {
    __shared__ float ts[32][33];
    const float* W = (blockIdx.z == 0) ? W0 : (blockIdx.z == 1) ? W1
                   : (blockIdx.z == 2) ? W2 : W3;
    __half* dst = Wt + (size_t)blockIdx.z * EE * EE;
    int x0 = blockIdx.x * 32, y0 = blockIdx.y * 32;
    int tx = threadIdx.x, ty = threadIdx.y;
    #pragma unroll
    for (int i = 0; i < 32; i += 8)
        ts[ty + i][tx] = W[(size_t)(y0 + ty + i) * EE + x0 + tx];
    __syncthreads();
    #pragma unroll
    for (int i = 0; i < 32; i += 8)
        dst[(size_t)(x0 + ty + i) * EE + y0 + tx] = __float2half_rn(ts[tx][ty + i]);
}
__global__ void concat_bias(const float* a, const float* b, const float* c, float* dst) {
    int i = threadIdx.x + blockIdx.x * blockDim.x;
    dst[i] = a[i]; dst[i + EE] = b[i]; dst[i + 2*EE] = c[i];
}

// ---------------------------------------------------------------- GEMM (fp16)
// C = A[M,1024] @ W + bias. 512 thr (16 warps), block tile 128x128, warp tile
// 32x32 (4x4 warp grid), Kc=64 double-buffered. 2 CTAs/SM -> 8 warps/SMSP.
// mode 1: fused QKV scatter to fp16 [b,h,n,d]; mode 0: fp32 row-major out.
#define GA_LD 72    // halves per row (64 + 8 pad)
#define GEMM_SMEM (2*2*128*GA_LD*2)   // 73728 B

__global__ __launch_bounds__(512, 2) void gemm_f16(
    const __half* __restrict__ A, const __half* __restrict__ Wbase,
    const float* __restrict__ bias, void* __restrict__ Cout, int mode)
{
    extern __shared__ __half shh[];
    __half* As = shh;                        // 2 x 128 x GA_LD
    __half* Bs = shh + 2 * 128 * GA_LD;      // 2 x 128 x GA_LD

    const int m0 = blockIdx.y * 128, n0 = blockIdx.x * 128;
    const int tid = threadIdx.x, lane = tid & 31, warp = tid >> 5;
    const int wm = warp & 3, wn = warp >> 2;     // 4x4 warps of 32x32
    const int g = lane >> 2, t = lane & 3;

    const __half* W = Wbase + (size_t)(n0 >> 10) * EE * EE;
    const int ncol0 = n0 & 1023;

    const uint32_t as_u = smem_u32(As), bs_u = smem_u32(Bs);
    const int laneq = lane & 15;
    const int a_r = laneq, a_c = (lane >> 4) * 8;
    const int bp_r = (lane >> 4) * 8 + (lane & 7), bp_c = ((lane >> 3) & 1) * 8;

    float acc[2][4][4];
    #pragma unroll
    for (int a = 0; a < 2; a++)
        #pragma unroll
        for (int b = 0; b < 4; b++)
            #pragma unroll
            for (int c = 0; c < 4; c++) acc[a][b][c] = 0.0f;

    auto loadTiles = [&](int kc, int buf) {
        __half* Ad = As + buf * 128 * GA_LD;
        __half* Bd = Bs + buf * 128 * GA_LD;
        #pragma unroll
        for (int i = 0; i < 2; i++) {
            int idx = tid + i * 512; int r = idx >> 3, c = idx & 7;
            cpa16(Ad + r * GA_LD + c * 8, A + (size_t)(m0 + r) * EE + kc + c * 8);
        }
        #pragma unroll
        for (int i = 0; i < 2; i++) {
            int idx = tid + i * 512; int r = idx >> 3, c = idx & 7;
            cpa16(Bd + r * GA_LD + c * 8, W + (size_t)(ncol0 + r) * EE + kc + c * 8);
        }
        CP_COMMIT();
    };

    loadTiles(0, 0);
    for (int j = 0; j < 16; j++) {
        CP_WAIT0();
        __syncthreads();
        if (j + 1 < 16) loadTiles((j + 1) * 64, (j + 1) & 1);

        const uint32_t Ab = as_u + ((j & 1) * 128 + wm * 32) * GA_LD * 2;
        const uint32_t Bb = bs_u + ((j & 1) * 128 + wn * 32) * GA_LD * 2;
        #pragma unroll
        for (int kc = 0; kc < 4; kc++) {
            uint32_t af[2][4];
            #pragma unroll
            for (int mt = 0; mt < 2; mt++)
                ldm_x4(af[mt], Ab + ((mt * 16 + a_r) * GA_LD + kc * 16 + a_c) * 2);
            #pragma unroll
            for (int np = 0; np < 2; np++) {
                uint32_t bq[4];
                ldm_x4(bq, Bb + ((np * 16 + bp_r) * GA_LD + kc * 16 + bp_c) * 2);
                #pragma unroll
                for (int mt = 0; mt < 2; mt++) {
                    mma16(acc[mt][2 * np],     af[mt], bq);
                    mma16(acc[mt][2 * np + 1], af[mt], bq + 2);
                }
            }
        }
    }

    // epilogue
    #pragma unroll
    for (int nt = 0; nt < 4; nt++) {
        int col = n0 + wn * 32 + nt * 8 + 2 * t;
        float b0 = bias[col], b1 = bias[col + 1];
        #pragma unroll
        for (int mt = 0; mt < 2; mt++) {
            int r0 = m0 + wm * 32 + mt * 16 + g;
            float v00 = acc[mt][nt][0] + b0, v01 = acc[mt][nt][1] + b1;
            float v10 = acc[mt][nt][2] + b0, v11 = acc[mt][nt][3] + b1;
            if (mode == 1) {
                __half* Cq = (__half*)Cout + (size_t)(col >> 10) * MM * EE;
                int col1 = col & 1023;
                int b  = r0 >> 11, h = col1 >> 6, dd = col1 & 63;
                int nn0 = r0 & 2047;
                size_t base = ((size_t)((b * HH + h) * NN)) * DD + dd;
                *(__half2*)(Cq + base + (size_t)nn0 * DD)       = __floats2half2_rn(v00, v01);
                *(__half2*)(Cq + base + (size_t)(nn0 + 8) * DD) = __floats2half2_rn(v10, v11);
            } else {
                float* Cf = (float*)Cout;
                *(float2*)(Cf + (size_t)r0 * EE + col)       = make_float2(v00, v01);
                *(float2*)(Cf + (size_t)(r0 + 8) * EE + col) = make_float2(v10, v11);
            }
        }
    }
}

// ---------------------------------------------------------------- attention
// R13 config: 128 thr (4 warps), q-tile 64; warp owns 16 rows. fp16 mma,
// register P, x4 pair fragments, exp2 softmax, 2-stage cp.async.
#define KS_LD 72    // halves (64 + 8 pad)
#define ATTN_SMEM (2*(64*KS_LD + 64*KS_LD)*2)   // 36864 B

__global__ __launch_bounds__(128) void attn_kernel(
    const __half* __restrict__ Q, const __half* __restrict__ K,
    const __half* __restrict__ V, __half* __restrict__ Aout)
{
    extern __shared__ __half shh[];
    __half* Ks = shh;                       // 2 x 64 x KS_LD
    __half* Vs = shh + 2 * 64 * KS_LD;      // 2 x 64 x KS_LD

    const int q0 = blockIdx.x * 64, bh = blockIdx.y;
    const int tid = threadIdx.x, lane = tid & 31, warp = tid >> 5;
    const int g = lane >> 2, t = lane & 3;
    const int laneq = lane & 15;

    const __half* Qg = Q + (size_t)bh * NN * DD + (size_t)q0 * DD;
    const __half* Kg = K + (size_t)bh * NN * DD;
    const __half* Vg = V + (size_t)bh * NN * DD;

    const uint32_t ks_u = smem_u32(Ks), vs_u = smem_u32(Vs);
    const int bp_r = (lane >> 4) * 8 + (lane & 7), bp_c = ((lane >> 3) & 1) * 8;
    const int vp_c = (lane >> 4) * 8;

    // Q fragments (fp16, unscaled): 4 k-chunks x 4 regs
    uint32_t qf[4][4];
    {
        const __half* p0 = Qg + (warp * 16 + g) * DD;
        const __half* p1 = p0 + 8 * DD;
        #pragma unroll
        for (int kc = 0; kc < 4; kc++) {
            qf[kc][0] = *(const uint32_t*)(p0 + kc * 16 + 2 * t);
            qf[kc][1] = *(const uint32_t*)(p1 + kc * 16 + 2 * t);
            qf[kc][2] = *(const uint32_t*)(p0 + kc * 16 + 2 * t + 8);
            qf[kc][3] = *(const uint32_t*)(p1 + kc * 16 + 2 * t + 8);
        }
    }

    float O[8][4];
    #pragma unroll
    for (int nt = 0; nt < 8; nt++)
        #pragma unroll
        for (int i = 0; i < 4; i++) O[nt][i] = 0.0f;
    float m0r = -1e30f, m1r = -1e30f, l0 = 0.0f, l1 = 0.0f;
    const float qsc = 0.03125f * 1.44269504f;    // (1/32)*log2(e)

    auto loadKV = [&](int j, int buf) {
        const __half* Kt = Kg + (size_t)j * 64 * DD;
        const __half* Vt = Vg + (size_t)j * 64 * DD;
        __half* Kd = Ks + buf * 64 * KS_LD;
        __half* Vd = Vs + buf * 64 * KS_LD;
        #pragma unroll
        for (int i = 0; i < 4; i++) {
            int idx = tid + i * 128; int r = idx >> 3, c = idx & 7;
            cpa16(Kd + r * KS_LD + c * 8, Kt + r * DD + c * 8);
        }
        #pragma unroll
        for (int i = 0; i < 4; i++) {
            int idx = tid + i * 128; int r = idx >> 3, c = idx & 7;
            cpa16(Vd + r * KS_LD + c * 8, Vt + r * DD + c * 8);
        }
        CP_COMMIT();
    };

    loadKV(0, 0);
    for (int j = 0; j < NN / 64; j++) {
        CP_WAIT0();
        __syncthreads();
        if (j + 1 < NN / 64) loadKV(j + 1, (j + 1) & 1);

        const uint32_t Kb = ks_u + (j & 1) * 64 * KS_LD * 2;
        const uint32_t Vb = vs_u + (j & 1) * 64 * KS_LD * 2;

        // S = Q K^T  (16 x 64 per warp; scale folded into softmax)
        float S[8][4];
        #pragma unroll
        for (int nt = 0; nt < 8; nt++)
            #pragma unroll
            for (int i = 0; i < 4; i++) S[nt][i] = 0.0f;
        #pragma unroll
        for (int kc = 0; kc < 4; kc++) {
            #pragma unroll
            for (int np = 0; np < 4; np++) {
                uint32_t bq[4];
                ldm_x4(bq, Kb + ((np * 16 + bp_r) * KS_LD + kc * 16 + bp_c) * 2);
                mma16(S[2 * np],     qf[kc], bq);
                mma16(S[2 * np + 1], qf[kc], bq + 2);
            }
        }

        // online softmax (exp2 domain, scale qsc)
        float mx0 = -1e30f, mx1 = -1e30f;
        #pragma unroll
        for (int nt = 0; nt < 8; nt++) {
            mx0 = fmaxf(mx0, fmaxf(S[nt][0], S[nt][1]));
            mx1 = fmaxf(mx1, fmaxf(S[nt][2], S[nt][3]));
        }
        mx0 = fmaxf(mx0, __shfl_xor_sync(0xffffffffu, mx0, 1));
        mx0 = fmaxf(mx0, __shfl_xor_sync(0xffffffffu, mx0, 2));
        mx1 = fmaxf(mx1, __shfl_xor_sync(0xffffffffu, mx1, 1));
        mx1 = fmaxf(mx1, __shfl_xor_sync(0xffffffffu, mx1, 2));
        float mn0 = fmaxf(m0r, qsc * mx0), mn1 = fmaxf(m1r, qsc * mx1);
        float a0 = exp2f(m0r - mn0), a1 = exp2f(m1r - mn1);
        float s0 = 0.0f, s1 = 0.0f;
        #pragma unroll
        for (int nt = 0; nt < 8; nt++) {
            float p00 = exp2f(fmaf(S[nt][0], qsc, -mn0));
            float p01 = exp2f(fmaf(S[nt][1], qsc, -mn0));
            float p10 = exp2f(fmaf(S[nt][2], qsc, -mn1));
            float p11 = exp2f(fmaf(S[nt][3], qsc, -mn1));
            s0 += p00 + p01; s1 += p10 + p11;
            S[nt][0] = p00; S[nt][1] = p01; S[nt][2] = p10; S[nt][3] = p11;
        }
        s0 += __shfl_xor_sync(0xffffffffu, s0, 1);
        s0 += __shfl_xor_sync(0xffffffffu, s0, 2);
        s1 += __shfl_xor_sync(0xffffffffu, s1, 1);
        s1 += __shfl_xor_sync(0xffffffffu, s1, 2);
        l0 = l0 * a0 + s0; l1 = l1 * a1 + s1;
        m0r = mn0; m1r = mn1;
        #pragma unroll
        for (int nt = 0; nt < 8; nt++) {
            O[nt][0] *= a0; O[nt][1] *= a0;
            O[nt][2] *= a1; O[nt][3] *= a1;
        }

        // O += P @ V  (P register-resident)
        #pragma unroll
        for (int kc = 0; kc < 4; kc++) {
            uint32_t pa[4];
            pa[0] = packh2(S[2*kc][0],     S[2*kc][1]);
            pa[1] = packh2(S[2*kc][2],     S[2*kc][3]);
            pa[2] = packh2(S[2*kc + 1][0], S[2*kc + 1][1]);
            pa[3] = packh2(S[2*kc + 1][2], S[2*kc + 1][3]);
            #pragma unroll
            for (int np = 0; np < 4; np++) {
                uint32_t bq[4];
                ldm_x4t(bq, Vb + ((kc * 16 + laneq) * KS_LD + np * 16 + vp_c) * 2);
                mma16(O[2 * np],     pa, bq);
                mma16(O[2 * np + 1], pa, bq + 2);
            }
        }
    }

    // write out fp16 [b, n, h*64+d]
    {
        int b = bh >> 4, h = bh & 15;
        float i0 = 1.0f / l0, i1 = 1.0f / l1;
        int r = q0 + warp * 16 + g;
        __half* d0 = Aout + ((size_t)(b * NN + r)) * EE + h * 64;
        __half* d1 = d0 + (size_t)8 * EE;
        #pragma unroll
        for (int nt = 0; nt < 8; nt++) {
            int c = nt * 8 + 2 * t;
            *(__half2*)(d0 + c) = __floats2half2_rn(O[nt][0] * i0, O[nt][1] * i0);
            *(__half2*)(d1 + c) = __floats2half2_rn(O[nt][2] * i1, O[nt][3] * i1);
        }
    }
}

// ---------------------------------------------------------------- launch
extern "C" void kernel_launch(void* const* d_in, const int* in_sizes, int n_in,
                              void* d_out, int out_size)
{
    const float* x  = (const float*)d_in[0];
    const float* Wq = (const float*)d_in[1];
    const float* bq = (const float*)d_in[2];
    const float* Wk = (const float*)d_in[3];
    const float* bk = (const float*)d_in[4];
    const float* Wv = (const float*)d_in[5];
    const float* bv = (const float*)d_in[6];
    const float* Wo = (const float*)d_in[7];
    const float* bo = (const float*)d_in[8];

    __half *Xp, *Wtp, *QKVp, *Ap;
    float *Bcp;
    cudaGetSymbolAddress((void**)&Xp,   g_X);
    cudaGetSymbolAddress((void**)&Wtp,  g_Wt);
    cudaGetSymbolAddress((void**)&Bcp,  g_Bc);
    cudaGetSymbolAddress((void**)&QKVp, g_QKV);
    cudaGetSymbolAddress((void**)&Ap,   g_A);

    cudaFuncSetAttribute(gemm_f16, cudaFuncAttributeMaxDynamicSharedMemorySize, GEMM_SMEM);
    cudaFuncSetAttribute(attn_kernel, cudaFuncAttributeMaxDynamicSharedMemorySize, ATTN_SMEM);

    {
        int n4x = MM * EE / 4;
        conv_x<<<(n4x + 255) / 256, 256>>>(x, Xp, n4x);
        conv_wt<<<dim3(32, 32, 4), dim3(32, 8)>>>(Wq, Wk, Wv, Wo, Wtp);
        concat_bias<<<4, 256>>>(bq, bk, bv, Bcp);
    }

    // fused QKV: N=3072
    gemm_f16<<<dim3(3 * EE / 128, MM / 128), 512, GEMM_SMEM>>>(Xp, Wtp, Bcp, QKVp, 1);

    attn_kernel<<<dim3(NN / 64, BB * HH), 128, ATTN_SMEM>>>(
        QKVp, QKVp + (size_t)MM * EE, QKVp + (size_t)2 * MM * EE, Ap);

    // O-projection (fp32 out)
    gemm_f16<<<dim3(EE / 128, MM / 128), 512, GEMM_SMEM>>>(
        Ap, Wtp + (size_t)3 * EE * EE, bo, d_out, 0);
}

// round 17
// speedup vs baseline: 1.6102x; 1.6102x over previous
#include <cuda_runtime.h>
#include <cuda_fp16.h>
#include <cstdint>

// MultiHeadAttention x[4,2048,1024], 16 heads, d=64, scale 1/sqrt(1024)
// fp16 mma.m16n8k16 (fp32 accum). GEMM: R13 config (256 thr, 64x32 warp
// tiles, Kc=64, 2-stage). Attention: ex2.approx.f16x2 softmax + tensor-core
// row sums (L = P @ ones), register-resident P.

#define BB 4
#define NN 2048
#define EE 1024
#define HH 16
#define DD 64
#define MM (BB*NN)      // 8192

__device__ __half g_X  [(size_t)MM*EE];     // fp16 x [M,K]
__device__ __half g_Wt [(size_t)4*EE*EE];   // fp16 W^T [N,K] x4
__device__ float  g_Bc [3*EE];              // concat bq,bk,bv (fp32)
__device__ __half g_QKV[(size_t)3*MM*EE];   // Q|K|V fp16 [b,h,n,d]
__device__ __half g_A  [(size_t)MM*EE];     // attn out fp16 [b,n,e]

// ---------------------------------------------------------------- helpers
__device__ __forceinline__ void mma16(float c[4], const uint32_t a[4], const uint32_t b[2]) {
    asm volatile("mma.sync.aligned.m16n8k16.row.col.f32.f16.f16.f32 "
                 "{%0,%1,%2,%3}, {%4,%5,%6,%7}, {%8,%9}, {%0,%1,%2,%3};\n"
                 : "+f"(c[0]), "+f"(c[1]), "+f"(c[2]), "+f"(c[3])
                 : "r"(a[0]), "r"(a[1]), "r"(a[2]), "r"(a[3]), "r"(b[0]), "r"(b[1]));
}
__device__ __forceinline__ void ldm_x4(uint32_t r[4], uint32_t addr) {
    asm volatile("ldmatrix.sync.aligned.m8n8.x4.shared.b16 {%0,%1,%2,%3}, [%4];"
                 : "=r"(r[0]), "=r"(r[1]), "=r"(r[2]), "=r"(r[3]) : "r"(addr));
}
__device__ __forceinline__ void ldm_x4t(uint32_t r[4], uint32_t addr) {
    asm volatile("ldmatrix.sync.aligned.m8n8.x4.trans.shared.b16 {%0,%1,%2,%3}, [%4];"
                 : "=r"(r[0]), "=r"(r[1]), "=r"(r[2]), "=r"(r[3]) : "r"(addr));
}
__device__ __forceinline__ void cpa16(void* smem, const void* g) {
    uint32_t s = (uint32_t)__cvta_generic_to_shared(smem);
    asm volatile("cp.async.cg.shared.global [%0], [%1], 16;\n" :: "r"(s), "l"(g));
}
#define CP_COMMIT() asm volatile("cp.async.commit_group;\n")
#define CP_WAIT0()  asm volatile("cp.async.wait_group 0;\n")
__device__ __forceinline__ uint32_t smem_u32(const void* p) {
    return (uint32_t)__cvta_generic_to_shared(p);
}
__device__ __forceinline__ uint32_t packh2(float lo, float hi) {
    __half2 h = __floats2half2_rn(lo, hi);
    return *(uint32_t*)&h;
}
__device__ __forceinline__ uint32_t ex2h2(uint32_t x) {
    uint32_t r; asm("ex2.approx.f16x2 %0, %1;" : "=r"(r) : "r"(x)); return r;
}

// ---------------------------------------------------------------- convs
__global__ void conv_x(const float* __restrict__ src, __half* __restrict__ dst, int n4) {
    int i = blockIdx.x * blockDim.x + threadIdx.x;
    if (i < n4) {
        float4 v = ((const float4*)src)[i];
        ((__half2*)dst)[2*i]     = __floats2half2_rn(v.x, v.y);
        ((__half2*)dst)[2*i + 1] = __floats2half2_rn(v.z, v.w);
    }
}
__global__ void conv_wt(const float* W0, const float* W1, const float* W2,
                        const float* W3, __half* __restrict__ Wt) {
    __shared__ float ts[32][33];
    const float* W = (blockIdx.z == 0) ? W0 : (blockIdx.z == 1) ? W1
                   : (blockIdx.z == 2) ? W2 : W3;
    __half* dst = Wt + (size_t)blockIdx.z * EE * EE;
    int x0 = blockIdx.x * 32, y0 = blockIdx.y * 32;
    int tx = threadIdx.x, ty = threadIdx.y;
    #pragma unroll
    for (int i = 0; i < 32; i += 8)
        ts[ty + i][tx] = W[(size_t)(y0 + ty + i) * EE + x0 + tx];
    __syncthreads();
    #pragma unroll
    for (int i = 0; i < 32; i += 8)
        dst[(size_t)(x0 + ty + i) * EE + y0 + tx] = __float2half_rn(ts[tx][ty + i]);
}
__global__ void concat_bias(const float* a, const float* b, const float* c, float* dst) {
    int i = threadIdx.x + blockIdx.x * blockDim.x;
    dst[i] = a[i]; dst[i + EE] = b[i]; dst[i + 2*EE] = c[i];
}

// ---------------------------------------------------------------- GEMM (fp16)
// R13 config: 256 thr (8 warps), block tile 128x128, warp 64x32, Kc=64,
// 2-stage cp.async. A fp16 [M,K]; Wt fp16 [N,K].
// mode 1: fused QKV scatter to fp16 [b,h,n,d]; mode 0: fp32 row-major out.
#define GA_LD 72    // halves per row (64 + 8 pad)
#define GEMM_SMEM (2*2*128*GA_LD*2)   // 73728 B

__global__ __launch_bounds__(256) void gemm_f16(
    const __half* __restrict__ A, const __half* __restrict__ Wbase,
    const float* __restrict__ bias, void* __restrict__ Cout, int mode)
{
    extern __shared__ __half shh[];
    __half* As = shh;                        // 2 x 128 x GA_LD
    __half* Bs = shh + 2 * 128 * GA_LD;      // 2 x 128 x GA_LD

    const int m0 = blockIdx.y * 128, n0 = blockIdx.x * 128;
    const int tid = threadIdx.x, lane = tid & 31, warp = tid >> 5;
    const int wm = warp & 1, wn = warp >> 1;     // warps: 2 (m64) x 4 (n32)
    const int g = lane >> 2, t = lane & 3;

    const __half* W = Wbase + (size_t)(n0 >> 10) * EE * EE;
    const int ncol0 = n0 & 1023;

    const uint32_t as_u = smem_u32(As), bs_u = smem_u32(Bs);
    const int laneq = lane & 15;
    const int a_r = laneq, a_c = (lane >> 4) * 8;
    const int bp_r = (lane >> 4) * 8 + (lane & 7), bp_c = ((lane >> 3) & 1) * 8;

    float acc[4][4][4];
    #pragma unroll
    for (int a = 0; a < 4; a++)
        #pragma unroll
        for (int b = 0; b < 4; b++)
            #pragma unroll
            for (int c = 0; c < 4; c++) acc[a][b][c] = 0.0f;

    auto loadTiles = [&](int kc, int buf) {
        __half* Ad = As + buf * 128 * GA_LD;
        __half* Bd = Bs + buf * 128 * GA_LD;
        #pragma unroll
        for (int i = 0; i < 4; i++) {
            int idx = tid + i * 256; int r = idx >> 3, c = idx & 7;
            cpa16(Ad + r * GA_LD + c * 8, A + (size_t)(m0 + r) * EE + kc + c * 8);
        }
        #pragma unroll
        for (int i = 0; i < 4; i++) {
            int idx = tid + i * 256; int r = idx >> 3, c = idx & 7;
            cpa16(Bd + r * GA_LD + c * 8, W + (size_t)(ncol0 + r) * EE + kc + c * 8);
        }
        CP_COMMIT();
    };

    loadTiles(0, 0);
    for (int j = 0; j < 16; j++) {
        CP_WAIT0();
        __syncthreads();
        if (j + 1 < 16) loadTiles((j + 1) * 64, (j + 1) & 1);

        const uint32_t Ab = as_u + ((j & 1) * 128 + wm * 64) * GA_LD * 2;
        const uint32_t Bb = bs_u + ((j & 1) * 128 + wn * 32) * GA_LD * 2;
        #pragma unroll
        for (int kc = 0; kc < 4; kc++) {
            uint32_t af[4][4];
            #pragma unroll
            for (int mt = 0; mt < 4; mt++)
                ldm_x4(af[mt], Ab + ((mt * 16 + a_r) * GA_LD + kc * 16 + a_c) * 2);
            #pragma unroll
            for (int np = 0; np < 2; np++) {
                uint32_t bq[4];
                ldm_x4(bq, Bb + ((np * 16 + bp_r) * GA_LD + kc * 16 + bp_c) * 2);
                #pragma unroll
                for (int mt = 0; mt < 4; mt++) {
                    mma16(acc[mt][2 * np],     af[mt], bq);
                    mma16(acc[mt][2 * np + 1], af[mt], bq + 2);
                }
            }
        }
    }

    // epilogue
    #pragma unroll
    for (int nt = 0; nt < 4; nt++) {
        int col = n0 + wn * 32 + nt * 8 + 2 * t;
        float b0 = bias[col], b1 = bias[col + 1];
        #pragma unroll
        for (int mt = 0; mt < 4; mt++) {
            int r0 = m0 + wm * 64 + mt * 16 + g;
            float v00 = acc[mt][nt][0] + b0, v01 = acc[mt][nt][1] + b1;
            float v10 = acc[mt][nt][2] + b0, v11 = acc[mt][nt][3] + b1;
            if (mode == 1) {
                __half* Cq = (__half*)Cout + (size_t)(col >> 10) * MM * EE;
                int col1 = col & 1023;
                int b  = r0 >> 11, h = col1 >> 6, dd = col1 & 63;
                int nn0 = r0 & 2047;
                size_t base = ((size_t)((b * HH + h) * NN)) * DD + dd;
                *(__half2*)(Cq + base + (size_t)nn0 * DD)       = __floats2half2_rn(v00, v01);
                *(__half2*)(Cq + base + (size_t)(nn0 + 8) * DD) = __floats2half2_rn(v10, v11);
            } else {
                float* Cf = (float*)Cout;
                *(float2*)(Cf + (size_t)r0 * EE + col)       = make_float2(v00, v01);
                *(float2*)(Cf + (size_t)(r0 + 8) * EE + col) = make_float2(v10, v11);
            }
        }
    }
}

// ---------------------------------------------------------------- attention
// 128 thr (4 warps), q-tile 64; warp owns 16 rows. fp16 mma, register P via
// ex2.approx.f16x2, row sums L = P @ ones on tensor core, 2-stage cp.async.
#define KS_LD 72    // halves (64 + 8 pad)
#define ATTN_SMEM (2*(64*KS_LD + 64*KS_LD)*2)   // 36864 B

__global__ __launch_bounds__(128) void attn_kernel(
    const __half* __restrict__ Q, const __half* __restrict__ K,
    const __half* __restrict__ V, __half* __restrict__ Aout)
{
    extern __shared__ __half shh[];
    __half* Ks = shh;                       // 2 x 64 x KS_LD
    __half* Vs = shh + 2 * 64 * KS_LD;      // 2 x 64 x KS_LD

    const int q0 = blockIdx.x * 64, bh = blockIdx.y;
    const int tid = threadIdx.x, lane = tid & 31, warp = tid >> 5;
    const int g = lane >> 2, t = lane & 3;
    const int laneq = lane & 15;

    const __half* Qg = Q + (size_t)bh * NN * DD + (size_t)q0 * DD;
    const __half* Kg = K + (size_t)bh * NN * DD;
    const __half* Vg = V + (size_t)bh * NN * DD;

    const uint32_t ks_u = smem_u32(Ks), vs_u = smem_u32(Vs);
    const int bp_r = (lane >> 4) * 8 + (lane & 7), bp_c = ((lane >> 3) & 1) * 8;
    const int vp_c = (lane >> 4) * 8;

    // Q fragments (fp16, unscaled): 4 k-chunks x 4 regs
    uint32_t qf[4][4];
    {
        const __half* p0 = Qg + (warp * 16 + g) * DD;
        const __half* p1 = p0 + 8 * DD;
        #pragma unroll
        for (int kc = 0; kc < 4; kc++) {
            qf[kc][0] = *(const uint32_t*)(p0 + kc * 16 + 2 * t);
            qf[kc][1] = *(const uint32_t*)(p1 + kc * 16 + 2 * t);
            qf[kc][2] = *(const uint32_t*)(p0 + kc * 16 + 2 * t + 8);
            qf[kc][3] = *(const uint32_t*)(p1 + kc * 16 + 2 * t + 8);
        }
    }

    float O[8][4];
    #pragma unroll
    for (int nt = 0; nt < 8; nt++)
        #pragma unroll
        for (int i = 0; i < 4; i++) O[nt][i] = 0.0f;
    float Lc[4] = {0.0f, 0.0f, 0.0f, 0.0f};       // row sums via P @ ones
    float m0r = -1e30f, m1r = -1e30f;
    const float qsc = 0.03125f * 1.44269504f;     // (1/32)*log2(e)
    const uint32_t ONES2 = 0x3C003C00u;           // (1.0h, 1.0h)
    const uint32_t bq_ones[2] = { ONES2, ONES2 };

    auto loadKV = [&](int j, int buf) {
        const __half* Kt = Kg + (size_t)j * 64 * DD;
        const __half* Vt = Vg + (size_t)j * 64 * DD;
        __half* Kd = Ks + buf * 64 * KS_LD;
        __half* Vd = Vs + buf * 64 * KS_LD;
        #pragma unroll
        for (int i = 0; i < 4; i++) {
            int idx = tid + i * 128; int r = idx >> 3, c = idx & 7;
            cpa16(Kd + r * KS_LD + c * 8, Kt + r * DD + c * 8);
        }
        #pragma unroll
        for (int i = 0; i < 4; i++) {
            int idx = tid + i * 128; int r = idx >> 3, c = idx & 7;
            cpa16(Vd + r * KS_LD + c * 8, Vt + r * DD + c * 8);
        }
        CP_COMMIT();
    };

    loadKV(0, 0);
    for (int j = 0; j < NN / 64; j++) {
        CP_WAIT0();
        __syncthreads();
        if (j + 1 < NN / 64) loadKV(j + 1, (j + 1) & 1);

        const uint32_t Kb = ks_u + (j & 1) * 64 * KS_LD * 2;
        const uint32_t Vb = vs_u + (j & 1) * 64 * KS_LD * 2;

        // S = Q K^T  (16 x 64 per warp; scale folded into softmax)
        float S[8][4];
        #pragma unroll
        for (int nt = 0; nt < 8; nt++)
            #pragma unroll
            for (int i = 0; i < 4; i++) S[nt][i] = 0.0f;
        #pragma unroll
        for (int kc = 0; kc < 4; kc++) {
            #pragma unroll
            for (int np = 0; np < 4; np++) {
                uint32_t bq[4];
                ldm_x4(bq, Kb + ((np * 16 + bp_r) * KS_LD + kc * 16 + bp_c) * 2);
                mma16(S[2 * np],     qf[kc], bq);
                mma16(S[2 * np + 1], qf[kc], bq + 2);
            }
        }

        // online max update (exp2 domain)
        float mx0 = -1e30f, mx1 = -1e30f;
        #pragma unroll
        for (int nt = 0; nt < 8; nt++) {
            mx0 = fmaxf(mx0, fmaxf(S[nt][0], S[nt][1]));
            mx1 = fmaxf(mx1, fmaxf(S[nt][2], S[nt][3]));
        }
        mx0 = fmaxf(mx0, __shfl_xor_sync(0xffffffffu, mx0, 1));
        mx0 = fmaxf(mx0, __shfl_xor_sync(0xffffffffu, mx0, 2));
        mx1 = fmaxf(mx1, __shfl_xor_sync(0xffffffffu, mx1, 1));
        mx1 = fmaxf(mx1, __shfl_xor_sync(0xffffffffu, mx1, 2));
        float mn0 = fmaxf(m0r, qsc * mx0), mn1 = fmaxf(m1r, qsc * mx1);
        float a0 = exp2f(m0r - mn0), a1 = exp2f(m1r - mn1);
        m0r = mn0; m1r = mn1;
        #pragma unroll
        for (int nt = 0; nt < 8; nt++) {
            O[nt][0] *= a0; O[nt][1] *= a0;
            O[nt][2] *= a1; O[nt][3] *= a1;
        }
        Lc[0] *= a0; Lc[1] *= a0; Lc[2] *= a1; Lc[3] *= a1;

        // P = ex2(S*qsc - m) packed fp16x2; O += P @ V; L += P @ ones
        #pragma unroll
        for (int kc = 0; kc < 4; kc++) {
            uint32_t pa[4];
            pa[0] = ex2h2(packh2(fmaf(S[2*kc][0],   qsc, -mn0),
                                 fmaf(S[2*kc][1],   qsc, -mn0)));
            pa[1] = ex2h2(packh2(fmaf(S[2*kc][2],   qsc, -mn1),
                                 fmaf(S[2*kc][3],   qsc, -mn1)));
            pa[2] = ex2h2(packh2(fmaf(S[2*kc+1][0], qsc, -mn0),
                                 fmaf(S[2*kc+1][1], qsc, -mn0)));
            pa[3] = ex2h2(packh2(fmaf(S[2*kc+1][2], qsc, -mn1),
                                 fmaf(S[2*kc+1][3], qsc, -mn1)));
            mma16(Lc, pa, bq_ones);
            #pragma unroll
            for (int np = 0; np < 4; np++) {
                uint32_t bq[4];
                ldm_x4t(bq, Vb + ((kc * 16 + laneq) * KS_LD + np * 16 + vp_c) * 2);
                mma16(O[2 * np],     pa, bq);
                mma16(O[2 * np + 1], pa, bq + 2);
            }
        }
    }

    // write out fp16 [b, n, h*64+d]
    {
        int b = bh >> 4, h = bh & 15;
        float i0 = 1.0f / Lc[0], i1 = 1.0f / Lc[2];
        int r = q0 + warp * 16 + g;
        __half* d0 = Aout + ((size_t)(b * NN + r)) * EE + h * 64;
        __half* d1 = d0 + (size_t)8 * EE;
        #pragma unroll
        for (int nt = 0; nt < 8; nt++) {
            int c = nt * 8 + 2 * t;
            *(__half2*)(d0 + c) = __floats2half2_rn(O[nt][0] * i0, O[nt][1] * i0);
            *(__half2*)(d1 + c) = __floats2half2_rn(O[nt][2] * i1, O[nt][3] * i1);
        }
    }
}

// ---------------------------------------------------------------- launch
extern "C" void kernel_launch(void* const* d_in, const int* in_sizes, int n_in,
                              void* d_out, int out_size)
{
    const float* x  = (const float*)d_in[0];
    const float* Wq = (const float*)d_in[1];
    const float* bq = (const float*)d_in[2];
    const float* Wk = (const float*)d_in[3];
    const float* bk = (const float*)d_in[4];
    const float* Wv = (const float*)d_in[5];
    const float* bv = (const float*)d_in[6];
    const float* Wo = (const float*)d_in[7];
    const float* bo = (const float*)d_in[8];

    __half *Xp, *Wtp, *QKVp, *Ap;
    float *Bcp;
    cudaGetSymbolAddress((void**)&Xp,   g_X);
    cudaGetSymbolAddress((void**)&Wtp,  g_Wt);
    cudaGetSymbolAddress((void**)&Bcp,  g_Bc);
    cudaGetSymbolAddress((void**)&QKVp, g_QKV);
    cudaGetSymbolAddress((void**)&Ap,   g_A);

    cudaFuncSetAttribute(gemm_f16, cudaFuncAttributeMaxDynamicSharedMemorySize, GEMM_SMEM);
    cudaFuncSetAttribute(attn_kernel, cudaFuncAttributeMaxDynamicSharedMemorySize, ATTN_SMEM);

    {
        int n4x = MM * EE / 4;
        conv_x<<<(n4x + 255) / 256, 256>>>(x, Xp, n4x);
        conv_wt<<<dim3(32, 32, 4), dim3(32, 8)>>>(Wq, Wk, Wv, Wo, Wtp);
        concat_bias<<<4, 256>>>(bq, bk, bv, Bcp);
    }

    // fused QKV: N=3072
    gemm_f16<<<dim3(3 * EE / 128, MM / 128), 256, GEMM_SMEM>>>(Xp, Wtp, Bcp, QKVp, 1);

    attn_kernel<<<dim3(NN / 64, BB * HH), 128, ATTN_SMEM>>>(
        QKVp, QKVp + (size_t)MM * EE, QKVp + (size_t)2 * MM * EE, Ap);

    // O-projection (fp32 out)
    gemm_f16<<<dim3(EE / 128, MM / 128), 256, GEMM_SMEM>>>(
        Ap, Wtp + (size_t)3 * EE * EE, bo, d_out, 0);
}